// round 14
// baseline (speedup 1.0000x reference)
#include <cuda_runtime.h>
#include <math.h>
#include <stdint.h>

#define B_ 4
#define T_ 2048
#define C_ 512
#define H_ 8
#define HD_ 64
#define TOPK_ 32
#define BH_ (B_*H_)          // 32
#define ROWS_ (BH_*T_)       // 65536
#define SPIKES_SZ ((size_t)B_*T_*C_)   // 4194304

// ------------------- cp.async helpers -------------------
__device__ __forceinline__ void cp_async16(void* smem_dst, const void* gsrc) {
    unsigned dst = (unsigned)__cvta_generic_to_shared(smem_dst);
    asm volatile("cp.async.cg.shared.global [%0], [%1], 16;" :: "r"(dst), "l"(gsrc));
}
__device__ __forceinline__ void cp_commit() {
    asm volatile("cp.async.commit_group;");
}
template<int N>
__device__ __forceinline__ void cp_wait() {
    asm volatile("cp.async.wait_group %0;" :: "n"(N));
}

// ------------------- scratch (device globals; no allocation) -------------------
__device__ float g_q[BH_*T_*HD_];        // [bh][t][d]
__device__ float g_k[BH_*T_*HD_];
__device__ float g_v[BH_*T_*HD_];
__device__ float g_scores[(size_t)ROWS_*T_];   // 537MB [row][tk]
__device__ float g_ctx[B_*T_*C_];        // [b][t][c]
__device__ float g_analog[B_*T_*C_];

// ------------------- GEMM: M=8192, N=512, K=512, cp.async double-buffered -------------------
#define A_STRIDE 36
template<int MODE>
__global__ void __launch_bounds__(256) k_gemm(const float* __restrict__ X,
    const float* __restrict__ Wq, const float* __restrict__ Wk, const float* __restrict__ Wv,
    const float* __restrict__ bq, const float* __restrict__ bk, const float* __restrict__ bv)
{
    extern __shared__ float smg[];
    float (*As)[128][A_STRIDE] = (float(*)[128][A_STRIDE])smg;                 // 2 x 128 x 36
    float (*Bs)[32][128]       = (float(*)[32][128])(smg + 2*128*A_STRIDE);    // 2 x 32 x 128

    const float* Xp   = (MODE == 0) ? X : g_ctx;
    const float* W    = (MODE == 0) ? (blockIdx.z == 0 ? Wq : (blockIdx.z == 1 ? Wk : Wv)) : Wq;
    const float* bias = (MODE == 0) ? (blockIdx.z == 0 ? bq : (blockIdx.z == 1 ? bk : bv)) : bq;
    float* O = 0;
    if (MODE == 0) O = (blockIdx.z == 0 ? g_q : (blockIdx.z == 1 ? g_k : g_v));
    else           O = g_analog;

    const int tid = threadIdx.x;
    const int tx = tid & 15, ty = tid >> 4;
    const int m0 = blockIdx.y * 128, n0 = blockIdx.x * 128;

    float acc[8][8];
    #pragma unroll
    for (int j = 0; j < 8; j++)
        #pragma unroll
        for (int i = 0; i < 8; i++) acc[j][i] = 0.0f;

    auto prefetch = [&](int k0, int buf) {
        #pragma unroll
        for (int it = 0; it < 4; it++) {
            int f4 = tid + 256 * it;
            int r = f4 >> 3, c = f4 & 7;
            cp_async16(&As[buf][r][c*4], &Xp[(size_t)(m0 + r) * 512 + k0 + c * 4]);
        }
        #pragma unroll
        for (int it = 0; it < 4; it++) {
            int f4 = tid + 256 * it;
            int r = f4 >> 5, c4 = f4 & 31;
            cp_async16(&Bs[buf][r][c4*4], &W[(size_t)(k0 + r) * 512 + n0 + c4 * 4]);
        }
        cp_commit();
    };

    prefetch(0, 0);

    for (int t = 0; t < 16; t++) {
        const int buf = t & 1;
        if (t < 15) {
            prefetch((t + 1) * 32, buf ^ 1);
            cp_wait<1>();
        } else {
            cp_wait<0>();
        }
        __syncthreads();

        #pragma unroll 8
        for (int kk = 0; kk < 32; kk++) {
            float a[8], b[8];
            #pragma unroll
            for (int j = 0; j < 8; j++) a[j] = As[buf][ty + 16*j][kk];
            #pragma unroll
            for (int i = 0; i < 8; i++) b[i] = Bs[buf][kk][tx + 16*i];
            #pragma unroll
            for (int j = 0; j < 8; j++)
                #pragma unroll
                for (int i = 0; i < 8; i++)
                    acc[j][i] += a[j] * b[i];
        }
        __syncthreads();
    }

    #pragma unroll
    for (int j = 0; j < 8; j++) {
        int m = m0 + ty + 16*j;
        #pragma unroll
        for (int i = 0; i < 8; i++) {
            int n = n0 + tx + 16*i;
            float val = acc[j][i] + bias[n];
            if (MODE == 0) {
                int b = m >> 11, t = m & 2047;
                int h = n >> 6, d = n & 63;
                O[(((size_t)(b * H_ + h)) * T_ + t) * HD_ + d] = val;
            } else {
                O[(size_t)m * 512 + n] = val;
            }
        }
    }
}

// ------------------- scores: swizzled vectorized microkernel -------------------
// Layout: rows 64 floats (256B) unpadded; 16B chunk c of row r stored at chunk c ^ ((r>>3)&15).
// Thread microtile: m = ty*8+j (contiguous), n = tx*8+i (contiguous).
//   b4[i] = LDS.128 at chunk dg^tx (i-independent -> immediate offsets; banks 2-way = 2-phase min)
//   a4    = LDS.128 at chunk dg^ty (j-independent; 2 addrs/warp, different groups -> conflict-free)
// Inner mix: 16 LDS.128 + 256 FFMA per dg -> FFMA-issue-limited.
// Epilogue: float4 score stores. smem: K 32KB + 2xQ 64KB = 98304B -> 2 CTA/SM.
#define QS_SZ (128 * 64)
__global__ void __launch_bounds__(256) k_scores(float* __restrict__ attn_out)
{
    extern __shared__ float sm[];
    float* Kd = sm;                               // 128 x 64, swizzled
    float* Qq = sm + 128 * 64;                    // 2 x 128 x 64, swizzled

    const int bh = blockIdx.z;
    const int n0 = blockIdx.y * 128;
    const int mq = blockIdx.x;                    // m-quarter: 4 m-tiles
    const float* Qb = g_q + (size_t)bh * T_ * HD_;
    const float* Kb = g_k + (size_t)bh * T_ * HD_;
    const int tid = threadIdx.x;
    const int tx = tid & 15, ty = tid >> 4;

    // prefetch Q tile (m-tile mt) into buffer buf, row-block-swizzled 16B chunks
    auto prefetchQ = [&](int mt, int buf) {
        const int m0 = mt * 128;
        float* Qd = Qq + buf * QS_SZ;
        #pragma unroll
        for (int it = 0; it < 8; it++) {
            int f = tid + 256 * it;               // 128 rows x 16 chunks
            int r = f >> 4, c = f & 15;
            int sc = c ^ ((r >> 3) & 15);
            cp_async16(&Qd[r * 64 + sc * 4], &Qb[(size_t)(m0 + r) * 64 + c * 4]);
        }
        cp_commit();
    };

    prefetchQ(mq * 4, 0);

    // K tile loaded once per block (plain loads, swizzled stores)
    #pragma unroll
    for (int it = 0; it < 8; it++) {
        int f = tid + 256 * it;
        int r = f >> 4, c = f & 15;
        float4 w = *(const float4*)&Kb[(size_t)(n0 + r) * 64 + c * 4];
        int sc = c ^ ((r >> 3) & 15);
        *(float4*)&Kd[r * 64 + sc * 4] = w;
    }

    float* Sb = g_scores + (size_t)bh * T_ * T_;
    const float4 z = make_float4(0.f, 0.f, 0.f, 0.f);

    for (int mi = 0; mi < 4; mi++) {
        const int buf = mi & 1;
        const int m0 = (mq * 4 + mi) * 128;
        if (mi < 3) {
            prefetchQ(mq * 4 + mi + 1, buf ^ 1);
            cp_wait<1>();
        } else {
            cp_wait<0>();
        }
        __syncthreads();                           // Q[buf] ready; K ready (first iter)

        const float* Qd = Qq + buf * QS_SZ;

        float acc[8][8];
        #pragma unroll
        for (int j = 0; j < 8; j++)
            #pragma unroll
            for (int i = 0; i < 8; i++) acc[j][i] = 0.0f;

        #pragma unroll 4
        for (int dg = 0; dg < 16; dg++) {          // d = dg*4 + dd, ascending
            float4 b4[8];
            const int boff = ((dg ^ tx) << 2);
            #pragma unroll
            for (int i = 0; i < 8; i++)
                b4[i] = *(const float4*)&Kd[(tx*8 + i) * 64 + boff];
            const int aoff = ((dg ^ ty) << 2);
            #pragma unroll
            for (int j = 0; j < 8; j++) {
                float4 a4 = *(const float4*)&Qd[(ty*8 + j) * 64 + aoff];
                #pragma unroll
                for (int i = 0; i < 8; i++) acc[j][i] += a4.x * b4[i].x;
                #pragma unroll
                for (int i = 0; i < 8; i++) acc[j][i] += a4.y * b4[i].y;
                #pragma unroll
                for (int i = 0; i < 8; i++) acc[j][i] += a4.z * b4[i].z;
                #pragma unroll
                for (int i = 0; i < 8; i++) acc[j][i] += a4.w * b4[i].w;
            }
        }

        // epilogue: vectorized score stores + zero-fill of attn output
        #pragma unroll
        for (int j = 0; j < 8; j++) {
            int m = m0 + ty*8 + j;
            float4 s0, s1;
            s0.x = acc[j][0] * 0.125f; s0.y = acc[j][1] * 0.125f;
            s0.z = acc[j][2] * 0.125f; s0.w = acc[j][3] * 0.125f;
            s1.x = acc[j][4] * 0.125f; s1.y = acc[j][5] * 0.125f;
            s1.z = acc[j][6] * 0.125f; s1.w = acc[j][7] * 0.125f;
            *(float4*)&Sb[(size_t)m * T_ + n0 + tx*8]     = s0;
            *(float4*)&Sb[(size_t)m * T_ + n0 + tx*8 + 4] = s1;

            size_t grow = (size_t)(bh * T_ + m);
            float4* dst = (float4*)(attn_out + grow * T_ + n0);
            dst[tx*2]   = z;
            dst[tx*2+1] = z;
        }
        __syncthreads();   // all warps done with Q[buf] before prefetch overwrites it
    }
}

// ------------------- fused top-32 + softmax + scatter + context gather (MLP=8) -------------------
__global__ void __launch_bounds__(256) k_topkctx(float* __restrict__ attn_out)
{
    const unsigned FULL = 0xffffffffu;
    int warp = threadIdx.x >> 5, lane = threadIdx.x & 31;
    int row = blockIdx.x * 8 + warp;
    const float* r = g_scores + (size_t)row * T_;

    float lv = -INFINITY;  // lane holds slot `lane` of descending sorted top-32
    int   li = 0;

    for (int cb = 0; cb < 64; cb += 8) {
        float e8[8];
        #pragma unroll
        for (int j = 0; j < 8; j++) e8[j] = __ldcs(&r[(cb + j) * 32 + lane]);  // 8 streaming loads in flight

        #pragma unroll
        for (int j = 0; j < 8; j++) {
            float e = e8[j];
            int idx = (cb + j) * 32 + lane;
            float thr = __shfl_sync(FULL, lv, 31);        // current min of list
            unsigned mask = __ballot_sync(FULL, e > thr);
            while (mask) {
                int src = __ffs(mask) - 1;
                mask &= mask - 1;
                float xv = __shfl_sync(FULL, e, src);
                int   xi = __shfl_sync(FULL, idx, src);
                unsigned ge = __ballot_sync(FULL, lv >= xv);   // entries ranked above x (stable)
                int pos = __popc(ge);
                float pv = __shfl_up_sync(FULL, lv, 1);
                int   pi = __shfl_up_sync(FULL, li, 1);
                if (lane >= pos) {
                    lv = (lane == pos) ? xv : pv;
                    li = (lane == pos) ? xi : pi;
                }
            }
        }
    }

    // softmax over the 32 selected values (lane 0 holds the max)
    float mx = __shfl_sync(FULL, lv, 0);
    float p = expf(lv - mx);
    float s = p;
    #pragma unroll
    for (int o = 16; o; o >>= 1) s += __shfl_xor_sync(FULL, s, o);
    p /= s;

    // scatter into attn output (row already zeroed by k_scores)
    attn_out[(size_t)row * T_ + li] = p;

    // context gather (identical arithmetic order to the former k_context)
    int bh = row >> 11, t = row & 2047;
    const float* Vb = g_v + (size_t)bh * T_ * HD_;
    float a0 = 0.f, a1 = 0.f;
    #pragma unroll
    for (int j = 0; j < 32; j++) {
        float pp = __shfl_sync(FULL, p, j);
        int   ix = __shfl_sync(FULL, li, j);
        const float* vr = Vb + (size_t)ix * HD_;
        a0 += pp * vr[lane];
        a1 += pp * vr[lane + 32];
    }
    int b = bh >> 3, h = bh & 7;
    float* o = g_ctx + ((size_t)(b * T_ + t)) * C_ + h * HD_;
    o[lane] = a0;
    o[lane + 32] = a1;
}

// ------------------- LayerNorm (two-pass, warp per row) -------------------
__global__ void __launch_bounds__(256) k_ln(const float* __restrict__ gamma,
                                            const float* __restrict__ beta)
{
    const unsigned FULL = 0xffffffffu;
    int warp = threadIdx.x >> 5, lane = threadIdx.x & 31;
    int row = blockIdx.x * 8 + warp;
    const float* x = g_analog + (size_t)row * C_;

    float v[16];
    float s = 0.f;
    #pragma unroll
    for (int i = 0; i < 16; i++) { v[i] = x[lane + 32 * i]; s += v[i]; }
    #pragma unroll
    for (int o = 16; o; o >>= 1) s += __shfl_xor_sync(FULL, s, o);
    float mu = s * (1.0f / 512.0f);

    float q = 0.f;
    #pragma unroll
    for (int i = 0; i < 16; i++) { float d = v[i] - mu; q += d * d; }
    #pragma unroll
    for (int o = 16; o; o >>= 1) q += __shfl_xor_sync(FULL, q, o);
    float var = q * (1.0f / 512.0f);
    float inv = 1.0f / sqrtf(var + 1e-5f);

    float* y = g_analog + (size_t)row * C_;
    #pragma unroll
    for (int i = 0; i < 16; i++) {
        int c = lane + 32 * i;
        y[c] = (v[i] - mu) * inv * gamma[c] + beta[c];
    }
}

// ------------------- adaptive LIF readout (one thread per (b,c) chain) -------------------
__global__ void __launch_bounds__(256) k_lif(float* __restrict__ out)
{
    int idx = blockIdx.x * 256 + threadIdx.x;   // 0..2047 -> (b, c)
    int b = idx >> 9, c = idx & 511;
    const float* x = g_analog + (size_t)b * T_ * C_ + c;
    float* o = out + (size_t)b * T_ * C_ + c;

    float vm = 0.f, ad = 0.f;
    #pragma unroll 4
    for (int t = 0; t < T_; t++) {
        float xt = x[(size_t)t * C_];
        vm = 0.9f * vm + xt;
        float th = 1.0f + 0.1f * ad;
        float u = vm - th;
        float sp = (u > 0.0f) ? 1.0f : 0.0f;
        vm = vm - sp * th;
        ad = 0.9f * ad + sp;
        o[(size_t)t * C_] = sp;
    }
}

// ------------------- launch -------------------
extern "C" void kernel_launch(void* const* d_in, const int* in_sizes, int n_in,
                              void* d_out, int out_size)
{
    const float* x     = (const float*)d_in[0];
    const float* Wq    = (const float*)d_in[1];
    const float* bq    = (const float*)d_in[2];
    const float* Wk    = (const float*)d_in[3];
    const float* bk    = (const float*)d_in[4];
    const float* Wv    = (const float*)d_in[5];
    const float* bv    = (const float*)d_in[6];
    const float* Wo    = (const float*)d_in[7];
    const float* bo    = (const float*)d_in[8];
    const float* gamma = (const float*)d_in[9];
    const float* beta  = (const float*)d_in[10];

    float* out      = (float*)d_out;
    float* out_attn = out + SPIKES_SZ;

    const int smem_gemm = (2 * 128 * A_STRIDE + 2 * 32 * 128) * 4;   // 69632 B
    cudaFuncSetAttribute(k_gemm<0>, cudaFuncAttributeMaxDynamicSharedMemorySize, smem_gemm);
    cudaFuncSetAttribute(k_gemm<1>, cudaFuncAttributeMaxDynamicSharedMemorySize, smem_gemm);

    // 1) QKV projections -> g_q/g_k/g_v in [bh][t][d] layout
    k_gemm<0><<<dim3(4, 64, 3), 256, smem_gemm>>>(x, Wq, Wk, Wv, bq, bk, bv);

    // 2) scores = Q K^T * scale (swizzled vectorized microkernel) + attn zero-fill
    const int smem_scores = (128 * 64 + 2 * 128 * 64) * 4;   // 98304 B -> 2 CTA/SM
    cudaFuncSetAttribute(k_scores, cudaFuncAttributeMaxDynamicSharedMemorySize, smem_scores);
    k_scores<<<dim3(4, 16, 32), 256, smem_scores>>>(out_attn);

    // 3) fused top-32 + softmax + scatter + context gather
    k_topkctx<<<ROWS_ / 8, 256>>>(out_attn);

    // 4) out projection -> g_analog
    k_gemm<1><<<dim3(4, 64, 1), 256, smem_gemm>>>(nullptr, Wo, Wo, Wo, bo, bo, bo);

    // 5) layernorm (in place)
    k_ln<<<(B_ * T_) / 8, 256>>>(gamma, beta);

    // 6) LIF readout -> spikes output
    k_lif<<<8, 256>>>(out);
}

// round 15
// speedup vs baseline: 1.0870x; 1.0870x over previous
#include <cuda_runtime.h>
#include <math.h>
#include <stdint.h>

#define B_ 4
#define T_ 2048
#define C_ 512
#define H_ 8
#define HD_ 64
#define TOPK_ 32
#define BH_ (B_*H_)          // 32
#define ROWS_ (BH_*T_)       // 65536
#define SPIKES_SZ ((size_t)B_*T_*C_)   // 4194304

// ------------------- cp.async helpers -------------------
__device__ __forceinline__ void cp_async16(void* smem_dst, const void* gsrc) {
    unsigned dst = (unsigned)__cvta_generic_to_shared(smem_dst);
    asm volatile("cp.async.cg.shared.global [%0], [%1], 16;" :: "r"(dst), "l"(gsrc));
}
__device__ __forceinline__ void cp_commit() {
    asm volatile("cp.async.commit_group;");
}
template<int N>
__device__ __forceinline__ void cp_wait() {
    asm volatile("cp.async.wait_group %0;" :: "n"(N));
}

// ------------------- scratch (device globals; no allocation) -------------------
__device__ float g_q[BH_*T_*HD_];        // [bh][t][d]
__device__ float g_k[BH_*T_*HD_];
__device__ float g_v[BH_*T_*HD_];
__device__ float g_scores[(size_t)ROWS_*T_];   // 537MB [row][tk]
__device__ float g_ctx[B_*T_*C_];        // [b][t][c]
__device__ float g_analog[B_*T_*C_];

// ------------------- GEMM: M=8192, N=512, K=512, cp.async double-buffered -------------------
#define A_STRIDE 36
template<int MODE>
__global__ void __launch_bounds__(256) k_gemm(const float* __restrict__ X,
    const float* __restrict__ Wq, const float* __restrict__ Wk, const float* __restrict__ Wv,
    const float* __restrict__ bq, const float* __restrict__ bk, const float* __restrict__ bv)
{
    extern __shared__ float smg[];
    float (*As)[128][A_STRIDE] = (float(*)[128][A_STRIDE])smg;                 // 2 x 128 x 36
    float (*Bs)[32][128]       = (float(*)[32][128])(smg + 2*128*A_STRIDE);    // 2 x 32 x 128

    const float* Xp   = (MODE == 0) ? X : g_ctx;
    const float* W    = (MODE == 0) ? (blockIdx.z == 0 ? Wq : (blockIdx.z == 1 ? Wk : Wv)) : Wq;
    const float* bias = (MODE == 0) ? (blockIdx.z == 0 ? bq : (blockIdx.z == 1 ? bk : bv)) : bq;
    float* O = 0;
    if (MODE == 0) O = (blockIdx.z == 0 ? g_q : (blockIdx.z == 1 ? g_k : g_v));
    else           O = g_analog;

    const int tid = threadIdx.x;
    const int tx = tid & 15, ty = tid >> 4;
    const int m0 = blockIdx.y * 128, n0 = blockIdx.x * 128;

    float acc[8][8];
    #pragma unroll
    for (int j = 0; j < 8; j++)
        #pragma unroll
        for (int i = 0; i < 8; i++) acc[j][i] = 0.0f;

    auto prefetch = [&](int k0, int buf) {
        #pragma unroll
        for (int it = 0; it < 4; it++) {
            int f4 = tid + 256 * it;
            int r = f4 >> 3, c = f4 & 7;
            cp_async16(&As[buf][r][c*4], &Xp[(size_t)(m0 + r) * 512 + k0 + c * 4]);
        }
        #pragma unroll
        for (int it = 0; it < 4; it++) {
            int f4 = tid + 256 * it;
            int r = f4 >> 5, c4 = f4 & 31;
            cp_async16(&Bs[buf][r][c4*4], &W[(size_t)(k0 + r) * 512 + n0 + c4 * 4]);
        }
        cp_commit();
    };

    prefetch(0, 0);

    for (int t = 0; t < 16; t++) {
        const int buf = t & 1;
        if (t < 15) {
            prefetch((t + 1) * 32, buf ^ 1);
            cp_wait<1>();
        } else {
            cp_wait<0>();
        }
        __syncthreads();

        #pragma unroll 8
        for (int kk = 0; kk < 32; kk++) {
            float a[8], b[8];
            #pragma unroll
            for (int j = 0; j < 8; j++) a[j] = As[buf][ty + 16*j][kk];
            #pragma unroll
            for (int i = 0; i < 8; i++) b[i] = Bs[buf][kk][tx + 16*i];
            #pragma unroll
            for (int j = 0; j < 8; j++)
                #pragma unroll
                for (int i = 0; i < 8; i++)
                    acc[j][i] += a[j] * b[i];
        }
        __syncthreads();
    }

    #pragma unroll
    for (int j = 0; j < 8; j++) {
        int m = m0 + ty + 16*j;
        #pragma unroll
        for (int i = 0; i < 8; i++) {
            int n = n0 + tx + 16*i;
            float val = acc[j][i] + bias[n];
            if (MODE == 0) {
                int b = m >> 11, t = m & 2047;
                int h = n >> 6, d = n & 63;
                O[(((size_t)(b * H_ + h)) * T_ + t) * HD_ + d] = val;
            } else {
                O[(size_t)m * 512 + n] = val;
            }
        }
    }
}

// ------------------- scores: per-bh 2048x2048x64 GEMM, *SCALE, + attn zero-fill -------------------
// (round-8 proven version — frozen)
__global__ void __launch_bounds__(256) k_scores(float* __restrict__ attn_out)
{
    extern __shared__ float sm[];
    float (*Qs)[65] = (float(*)[65])sm;               // 128 x 65
    float (*Ks)[65] = (float(*)[65])(sm + 128 * 65);  // 128 x 65

    const int bh = blockIdx.z;
    const float* Qb = g_q + (size_t)bh * T_ * HD_;
    const float* Kb = g_k + (size_t)bh * T_ * HD_;
    const int tid = threadIdx.x;
    const int tx = tid & 15, ty = tid >> 4;
    const int m0 = blockIdx.y * 128, n0 = blockIdx.x * 128;

    #pragma unroll
    for (int it = 0; it < 8; it++) {   // 2048 float4 per tile
        int f4 = tid + 256 * it;
        int r = f4 >> 4, c4 = f4 & 15;
        float4 v = *(const float4*)&Qb[(size_t)(m0 + r) * 64 + c4 * 4];
        Qs[r][c4*4+0] = v.x; Qs[r][c4*4+1] = v.y; Qs[r][c4*4+2] = v.z; Qs[r][c4*4+3] = v.w;
        float4 w = *(const float4*)&Kb[(size_t)(n0 + r) * 64 + c4 * 4];
        Ks[r][c4*4+0] = w.x; Ks[r][c4*4+1] = w.y; Ks[r][c4*4+2] = w.z; Ks[r][c4*4+3] = w.w;
    }
    __syncthreads();

    float acc[8][8];
    #pragma unroll
    for (int j = 0; j < 8; j++)
        #pragma unroll
        for (int i = 0; i < 8; i++) acc[j][i] = 0.0f;

    #pragma unroll 8
    for (int d = 0; d < 64; d++) {
        float a[8], b[8];
        #pragma unroll
        for (int j = 0; j < 8; j++) a[j] = Qs[ty + 16*j][d];
        #pragma unroll
        for (int i = 0; i < 8; i++) b[i] = Ks[tx + 16*i][d];
        #pragma unroll
        for (int j = 0; j < 8; j++)
            #pragma unroll
            for (int i = 0; i < 8; i++)
                acc[j][i] += a[j] * b[i];
    }

    float* Sb = g_scores + (size_t)bh * T_ * T_;
    const float4 z = make_float4(0.f, 0.f, 0.f, 0.f);
    #pragma unroll
    for (int j = 0; j < 8; j++) {
        int m = m0 + ty + 16*j;
        #pragma unroll
        for (int i = 0; i < 8; i++) {
            int n = n0 + tx + 16*i;
            Sb[(size_t)m * T_ + n] = acc[j][i] * 0.125f;
        }
        // zero-fill this block's tile of the attn output (hidden under GEMM compute)
        size_t grow = (size_t)(bh * T_ + m);
        float4* dst = (float4*)(attn_out + grow * T_ + n0);
        dst[tx*2]   = z;
        dst[tx*2+1] = z;
    }
}

// ------------------- fused top-32 + softmax + scatter + context gather -------------------
// float4 streaming loads (16 per row, 4KB in flight/warp). Candidate order differs from the
// scalar version but with no exact score ties the selected set and its value-sorted order
// are identical -> bit-identical outputs.
__global__ void __launch_bounds__(256) k_topkctx(float* __restrict__ attn_out)
{
    const unsigned FULL = 0xffffffffu;
    int warp = threadIdx.x >> 5, lane = threadIdx.x & 31;
    int row = blockIdx.x * 8 + warp;
    const float4* r4 = (const float4*)(g_scores + (size_t)row * T_);

    float lv = -INFINITY;  // lane holds slot `lane` of descending sorted top-32
    int   li = 0;

    for (int cb = 0; cb < 16; cb += 8) {
        float4 e8[8];
        #pragma unroll
        for (int j = 0; j < 8; j++) e8[j] = __ldcs(&r4[(cb + j) * 32 + lane]);  // 8 x 128B in flight

        #pragma unroll
        for (int j = 0; j < 8; j++) {
            float v4[4] = {e8[j].x, e8[j].y, e8[j].z, e8[j].w};
            int base = ((cb + j) * 32 + lane) * 4;
            #pragma unroll
            for (int k = 0; k < 4; k++) {
                float e = v4[k];
                int idx = base + k;
                float thr = __shfl_sync(FULL, lv, 31);        // current min of list
                unsigned mask = __ballot_sync(FULL, e > thr);
                while (mask) {
                    int src = __ffs(mask) - 1;
                    mask &= mask - 1;
                    float xv = __shfl_sync(FULL, e, src);
                    int   xi = __shfl_sync(FULL, idx, src);
                    unsigned ge = __ballot_sync(FULL, lv >= xv);   // entries ranked above x
                    int pos = __popc(ge);
                    float pv = __shfl_up_sync(FULL, lv, 1);
                    int   pi = __shfl_up_sync(FULL, li, 1);
                    if (lane >= pos) {
                        lv = (lane == pos) ? xv : pv;
                        li = (lane == pos) ? xi : pi;
                    }
                }
            }
        }
    }

    // softmax over the 32 selected values (lane 0 holds the max)
    float mx = __shfl_sync(FULL, lv, 0);
    float p = expf(lv - mx);
    float s = p;
    #pragma unroll
    for (int o = 16; o; o >>= 1) s += __shfl_xor_sync(FULL, s, o);
    p /= s;

    // scatter into attn output (row already zeroed by k_scores)
    attn_out[(size_t)row * T_ + li] = p;

    // context gather (identical arithmetic order to the former k_context)
    int bh = row >> 11, t = row & 2047;
    const float* Vb = g_v + (size_t)bh * T_ * HD_;
    float a0 = 0.f, a1 = 0.f;
    #pragma unroll
    for (int j = 0; j < 32; j++) {
        float pp = __shfl_sync(FULL, p, j);
        int   ix = __shfl_sync(FULL, li, j);
        const float* vr = Vb + (size_t)ix * HD_;
        a0 += pp * vr[lane];
        a1 += pp * vr[lane + 32];
    }
    int b = bh >> 3, h = bh & 7;
    float* o = g_ctx + ((size_t)(b * T_ + t)) * C_ + h * HD_;
    o[lane] = a0;
    o[lane + 32] = a1;
}

// ------------------- LayerNorm (two-pass, warp per row) -------------------
__global__ void __launch_bounds__(256) k_ln(const float* __restrict__ gamma,
                                            const float* __restrict__ beta)
{
    const unsigned FULL = 0xffffffffu;
    int warp = threadIdx.x >> 5, lane = threadIdx.x & 31;
    int row = blockIdx.x * 8 + warp;
    const float* x = g_analog + (size_t)row * C_;

    float v[16];
    float s = 0.f;
    #pragma unroll
    for (int i = 0; i < 16; i++) { v[i] = x[lane + 32 * i]; s += v[i]; }
    #pragma unroll
    for (int o = 16; o; o >>= 1) s += __shfl_xor_sync(FULL, s, o);
    float mu = s * (1.0f / 512.0f);

    float q = 0.f;
    #pragma unroll
    for (int i = 0; i < 16; i++) { float d = v[i] - mu; q += d * d; }
    #pragma unroll
    for (int o = 16; o; o >>= 1) q += __shfl_xor_sync(FULL, q, o);
    float var = q * (1.0f / 512.0f);
    float inv = 1.0f / sqrtf(var + 1e-5f);

    float* y = g_analog + (size_t)row * C_;
    #pragma unroll
    for (int i = 0; i < 16; i++) {
        int c = lane + 32 * i;
        y[c] = (v[i] - mu) * inv * gamma[c] + beta[c];
    }
}

// ------------------- adaptive LIF readout (one thread per (b,c) chain, 8-deep load batch) -------------------
__global__ void __launch_bounds__(256) k_lif(float* __restrict__ out)
{
    int idx = blockIdx.x * 256 + threadIdx.x;   // 0..2047 -> (b, c)
    int b = idx >> 9, c = idx & 511;
    const float* x = g_analog + (size_t)b * T_ * C_ + c;
    float* o = out + (size_t)b * T_ * C_ + c;

    float vm = 0.f, ad = 0.f;
    for (int t0 = 0; t0 < T_; t0 += 8) {
        float xt8[8];
        #pragma unroll
        for (int j = 0; j < 8; j++) xt8[j] = x[(size_t)(t0 + j) * C_];   // 8 loads in flight
        #pragma unroll
        for (int j = 0; j < 8; j++) {
            vm = 0.9f * vm + xt8[j];
            float th = 1.0f + 0.1f * ad;
            float u = vm - th;
            float sp = (u > 0.0f) ? 1.0f : 0.0f;
            vm = vm - sp * th;
            ad = 0.9f * ad + sp;
            o[(size_t)(t0 + j) * C_] = sp;
        }
    }
}

// ------------------- launch -------------------
extern "C" void kernel_launch(void* const* d_in, const int* in_sizes, int n_in,
                              void* d_out, int out_size)
{
    const float* x     = (const float*)d_in[0];
    const float* Wq    = (const float*)d_in[1];
    const float* bq    = (const float*)d_in[2];
    const float* Wk    = (const float*)d_in[3];
    const float* bk    = (const float*)d_in[4];
    const float* Wv    = (const float*)d_in[5];
    const float* bv    = (const float*)d_in[6];
    const float* Wo    = (const float*)d_in[7];
    const float* bo    = (const float*)d_in[8];
    const float* gamma = (const float*)d_in[9];
    const float* beta  = (const float*)d_in[10];

    float* out      = (float*)d_out;
    float* out_attn = out + SPIKES_SZ;

    const int smem_gemm = (2 * 128 * A_STRIDE + 2 * 32 * 128) * 4;   // 69632 B
    cudaFuncSetAttribute(k_gemm<0>, cudaFuncAttributeMaxDynamicSharedMemorySize, smem_gemm);
    cudaFuncSetAttribute(k_gemm<1>, cudaFuncAttributeMaxDynamicSharedMemorySize, smem_gemm);

    // 1) QKV projections -> g_q/g_k/g_v in [bh][t][d] layout
    k_gemm<0><<<dim3(4, 64, 3), 256, smem_gemm>>>(x, Wq, Wk, Wv, bq, bk, bv);

    // 2) scores = Q K^T * scale (batched over 32 bh) + zero-fill attn output
    const int smem_scores = 2 * 128 * 65 * 4;
    cudaFuncSetAttribute(k_scores, cudaFuncAttributeMaxDynamicSharedMemorySize, smem_scores);
    k_scores<<<dim3(16, 16, 32), 256, smem_scores>>>(out_attn);

    // 3) fused top-32 + softmax + scatter + context gather
    k_topkctx<<<ROWS_ / 8, 256>>>(out_attn);

    // 4) out projection -> g_analog
    k_gemm<1><<<dim3(4, 64, 1), 256, smem_gemm>>>(nullptr, Wo, Wo, Wo, bo, bo, bo);

    // 5) layernorm (in place)
    k_ln<<<(B_ * T_) / 8, 256>>>(gamma, beta);

    // 6) LIF readout -> spikes output
    k_lif<<<8, 256>>>(out);
}